// round 17
// baseline (speedup 1.0000x reference)
#include <cuda_runtime.h>
#include <stdint.h>

// Problem constants
#define BB 4
#define CC 8192
#define HH 32
#define WW 32
#define HW 1024                 // H*W
#define CHW (CC * HW)           // 8388608
#define NPIX 4096               // B*H*W
#define ROWS 128                // B*H
#define NCHUNK 16
#define CHUNK (CC / NCHUNK)     // 512
#define DD 256                  // embedding dim
#define DS2 32
#define OH_ELEMS ((size_t)BB * CC * HW)  // 33554432

#define NRED 2048               // reduce-role blocks (even bids < 4096)
#define NZERO 2048              // zero-role blocks (odd bids < 4096)
#define NW ROWS                 // 128 waiter blocks (bids 4096..4223)
#define GRID (NRED + NZERO + NW)

// Packed per-(pixel,chunk) partials: {mxg, idx_as_float_bits, s, sx}
__device__ float4 g_pack[NPIX][NCHUNK];
__device__ int    g_rowcnt[ROWS];   // W resets after consuming (replay-safe)
__device__ int    g_fidx[NPIX];     // fully rewritten each launch
__device__ float  g_klrow[ROWS];
__device__ int    g_wdone;          // last W resets

// ---------------------------------------------------------------------------
// kAll: grid 4224.
//  bid<4096, even : R block (row,chunk) — winner hot loop + R12-proven publish
//  bid<4096, odd  : zero block — winner code, completely untouched
//  bid>=4096      : W block (one per row) — poll row ready, combine, gather ->
//                   quantized, per-row KL (+ last W writes KL scalar)
// ---------------------------------------------------------------------------
__global__ __launch_bounds__(256, 6) void kAll(const float* __restrict__ x,
                                               const float* __restrict__ g,
                                               const float* __restrict__ emb,
                                               float* __restrict__ out,
                                               size_t kl_off, size_t oh_off) {
    const int bid = blockIdx.x;
    const int tid = threadIdx.x;

    if (bid < NRED + NZERO) {
        if (bid & 1) {
            // ---------------- zero role (untouched) ----------------
            const size_t zid = (size_t)(bid >> 1);
            float* oh = out + oh_off;
            uintptr_t addr = (uintptr_t)oh;
            int head = (int)(((16u - (unsigned)(addr & 15u)) & 15u) >> 2);
            size_t t = zid * 256 + tid;
            size_t nth = (size_t)NZERO * 256;

            if (t < (size_t)head) oh[t] = 0.0f;

            size_t n4 = (OH_ELEMS - head) >> 2;
            float4* o4 = (float4*)(oh + head);
            float4 z = make_float4(0.f, 0.f, 0.f, 0.f);
            for (size_t i = t; i < n4; i += nth) __stcs(&o4[i], z);

            size_t tail0 = (size_t)head + (n4 << 2);
            size_t ntail = OH_ELEMS - tail0;
            if (t < ntail) oh[tail0 + t] = 0.0f;
            return;
        }

        // ---------------- reduce role (winner hot loop) ----------------
        const int rid = bid >> 1;
        const int chunk = rid & 15;
        const int row   = rid >> 4;
        const int b = row >> 5, h = row & 31;
        const int warp = tid >> 5, lane = tid & 31;
        const int csub = lane >> 3, wg = lane & 7;

        const size_t rowbase = (size_t)b * CHW + (size_t)h * WW + (size_t)wg * 4;
        const int c0 = chunk * CHUNK + warp * 4 + csub;

        float mxg[4], s[4], sx[4];
        int ixg[4];
#pragma unroll
        for (int j = 0; j < 4; j++) {
            mxg[j] = -1e30f; ixg[j] = 0; s[j] = 0.f; sx[j] = 0.f;
        }

#pragma unroll 4
        for (int k = 0; k < CHUNK / 32; k++) {
            const int c = c0 + k * 32;
            const float4 xv = __ldcs((const float4*)(x + rowbase + (size_t)c * HW));
            const float4 gv = __ldcs((const float4*)(g + rowbase + (size_t)c * HW));
            const float xs[4] = {xv.x, xv.y, xv.z, xv.w};
            const float gs[4] = {gv.x, gv.y, gv.z, gv.w};
#pragma unroll
            for (int j = 0; j < 4; j++) {
                const float xx = xs[j];
                const float v = xx + gs[j];
                if (v > mxg[j]) { mxg[j] = v; ixg[j] = c; }  // '>' keeps first
                sx[j] += xx;
                s[j]  += __expf(xx);
            }
        }

#pragma unroll
        for (int off = 8; off < 32; off <<= 1) {
#pragma unroll
            for (int j = 0; j < 4; j++) {
                float vm = __shfl_xor_sync(0xffffffffu, mxg[j], off);
                int   vi = __shfl_xor_sync(0xffffffffu, ixg[j], off);
                if (vm > mxg[j] || (vm == mxg[j] && vi < ixg[j])) { mxg[j] = vm; ixg[j] = vi; }
                s[j]  += __shfl_xor_sync(0xffffffffu, s[j],  off);
                sx[j] += __shfl_xor_sync(0xffffffffu, sx[j], off);
            }
        }

        __shared__ float sh_mxg[8][8][4];
        __shared__ int   sh_ixg[8][8][4];
        __shared__ float sh_s  [8][8][4];
        __shared__ float sh_sx [8][8][4];

        if (csub == 0) {
#pragma unroll
            for (int j = 0; j < 4; j++) {
                sh_mxg[warp][wg][j] = mxg[j];
                sh_ixg[warp][wg][j] = ixg[j];
                sh_s  [warp][wg][j] = s[j];
                sh_sx [warp][wg][j] = sx[j];
            }
        }
        __syncthreads();

        if (tid < 32) {
            const int wg2 = tid >> 2, j = tid & 3;
            float M = -1e30f; int I = 0;
            float S = 0.f, SX = 0.f;
#pragma unroll
            for (int w = 0; w < 8; w++) {
                float vm = sh_mxg[w][wg2][j]; int vi = sh_ixg[w][wg2][j];
                if (vm > M || (vm == M && vi < I)) { M = vm; I = vi; }
                S  += sh_s [w][wg2][j];
                SX += sh_sx[w][wg2][j];
            }
            const int p = row * 32 + wg2 * 4 + j;
            g_pack[p][chunk] = make_float4(M, __int_as_float(I), S, SX);
            __threadfence();    // R12-proven: only ~512B of stores to order
            __syncwarp();
            if (tid == 0) atomicAdd(&g_rowcnt[row], 1);
        }
        return;
    }

    // ======================= W block (one per row) =======================
    const int row = bid - (NRED + NZERO);
    const int b = row >> 5, h = row & 31;

    __shared__ int   sidx[32];
    __shared__ float sterm[32];
    __shared__ float sm[32][DS2 + 1];
    __shared__ int   s_fin;

    // Acquire-poll: single thread, negligible traffic.
    if (tid == 0) {
        int v;
        do {
            asm volatile("ld.acquire.gpu.global.s32 %0, [%1];"
                         : "=r"(v) : "l"(&g_rowcnt[row]) : "memory");
            if (v >= NCHUNK) break;
            __nanosleep(128);
        } while (true);
    }
    __syncthreads();

    // ---- parallel combine: pixel = tid>>3, chunk-group = tid&7 ----
    {
        const int px = tid >> 3, cg = tid & 7;
        const int p = row * 32 + px;
        const float4 a = g_pack[p][cg * 2 + 0];
        const float4 c = g_pack[p][cg * 2 + 1];

        float M = a.x; int I = __float_as_int(a.y);
        float S = a.z, SX = a.w;
        {
            const int vi = __float_as_int(c.y);
            if (c.x > M || (c.x == M && vi < I)) { M = c.x; I = vi; }
            S += c.z; SX += c.w;
        }
#pragma unroll
        for (int off = 1; off < 8; off <<= 1) {
            float vm = __shfl_xor_sync(0xffffffffu, M, off);
            int   vi = __shfl_xor_sync(0xffffffffu, I, off);
            if (vm > M || (vm == M && vi < I)) { M = vm; I = vi; }
            S  += __shfl_xor_sync(0xffffffffu, S,  off);
            SX += __shfl_xor_sync(0xffffffffu, SX, off);
        }
        if (cg == 0) {
            sidx[px] = I;
            g_fidx[row * 32 + px] = I;
            const float LOGT = -9.010913347279288f;   // -log(8192)
            sterm[px] = LOGT - SX * (1.0f / 8192.0f) + logf(S);
        }
    }
    __syncthreads();

    if (tid == 0) g_rowcnt[row] = 0;   // reset for next graph replay

    // ---- emb gather -> quantized (8 d-slices; winner transpose) ----
#pragma unroll
    for (int ds = 0; ds < 8; ds++) {
        {
            const int r = tid >> 3, c4 = tid & 7;
            const float4 v = __ldg((const float4*)(emb + (size_t)sidx[r] * DD
                                                   + ds * DS2 + c4 * 4));
            sm[r][c4 * 4 + 0] = v.x;
            sm[r][c4 * 4 + 1] = v.y;
            sm[r][c4 * 4 + 2] = v.z;
            sm[r][c4 * 4 + 3] = v.w;
        }
        __syncthreads();
        {
            const int d = tid >> 3, w4 = tid & 7;
            float4 v;
            v.x = sm[w4 * 4 + 0][d];
            v.y = sm[w4 * 4 + 1][d];
            v.z = sm[w4 * 4 + 2][d];
            v.w = sm[w4 * 4 + 3][d];
            *(float4*)(out + (size_t)b * (DD * HW)
                           + (size_t)(ds * DS2 + d) * HW
                           + (size_t)h * WW + w4 * 4) = v;
        }
        __syncthreads();
    }

    // ---- KL: row sum -> g_klrow; last W writes the scalar directly ----
    if (tid < 32) {
        float term = sterm[tid];
#pragma unroll
        for (int off = 16; off > 0; off >>= 1)
            term += __shfl_xor_sync(0xffffffffu, term, off);
        if (tid == 0) {
            g_klrow[row] = term;
            __threadfence();
            s_fin = (atomicAdd(&g_wdone, 1) == NW - 1);
        }
    }
    __syncthreads();

    if (s_fin && tid < 32) {
        __threadfence();
        float acc = 0.f;
#pragma unroll
        for (int k = 0; k < ROWS / 32; k++) acc += g_klrow[k * 32 + tid];
#pragma unroll
        for (int off = 16; off > 0; off >>= 1)
            acc += __shfl_xor_sync(0xffffffffu, acc, off);
        if (tid == 0) {
            out[kl_off] = acc * 0.0625f;   // COMMITMENT_COST / B (direct store)
            g_wdone = 0;                   // reset for replay
        }
    }
}

// ---------------------------------------------------------------------------
// kOnes: the 4096 one_hot ones, after ALL zeros via the kernel boundary.
// One coalesced g_fidx load + one scattered store per thread. ~1us.
// ---------------------------------------------------------------------------
__global__ __launch_bounds__(256) void kOnes(float* __restrict__ out,
                                             size_t oh_off) {
    const int p = blockIdx.x * 256 + threadIdx.x;   // 16 x 256 = 4096
    const int b = p >> 10, hw = p & 1023;
    const int I = g_fidx[p];
    out[oh_off + (size_t)b * CHW + (size_t)I * HW + hw] = 1.0f;
}

// ---------------------------------------------------------------------------
extern "C" void kernel_launch(void* const* d_in, const int* in_sizes, int n_in,
                              void* d_out, int out_size) {
    const float* x   = (const float*)d_in[0];
    const float* emb = (const float*)d_in[1];
    const float* gum = (const float*)d_in[2];
    float* out = (float*)d_out;

    // Output layout: [quantized (1048576)] [kl (1)] [one_hot (33554432)]
    const size_t oh_off = (size_t)out_size - OH_ELEMS;
    const size_t kl_off = oh_off - 1;

    kAll<<<GRID, 256>>>(x, gum, emb, out, kl_off, oh_off);
    kOnes<<<NPIX / 256, 256>>>(out, oh_off);
}